// round 17
// baseline (speedup 1.0000x reference)
#include <cuda_runtime.h>
#include <cstdint>

#define BB 16
#define VV 8
#define SS 256
#define KK 66
#define NSEQ 128                 // B*V
#define NBLK 64                  // 2 sequences per block
#define ROWS (BB*SS*SS)          // 1,048,576 argmax rows
#define TILE (SS*KK)             // 16896 floats per sequence

__device__ float g_part[NSEQ];
__device__ unsigned int g_cnt;   // zero-init; self-resets each launch

__device__ __forceinline__ void ffma2(unsigned long long& d,
                                      unsigned long long a,
                                      unsigned long long b)
{
    asm("fma.rn.f32x2 %0, %1, %2, %0;" : "+l"(d) : "l"(a), "l"(b));
}

// ---------------- argmax over last dim of log_pa (B,S,S,K) ----------------
// Proven: 2048x256, RPI=4, no smem, occ 82%, ~5.7 TB/s (~50us).
__global__ void __launch_bounds__(256) argmax_kernel(const float* __restrict__ lp,
                                                     float* __restrict__ out)
{
    const int lane  = threadIdx.x & 31;
    const int gwarp = (blockIdx.x * blockDim.x + threadIdx.x) >> 5;
    const int nwarp = (gridDim.x * blockDim.x) >> 5;

    for (int base = gwarp * 4; base < ROWS; base += nwarp * 4) {
        float best[4]; int bi[4];
#pragma unroll
        for (int r = 0; r < 4; ++r) {
            const float* p = lp + (size_t)(base + r) * KK + lane;
            float v0 = __ldg(p);
            float v1 = __ldg(p + 32);
            best[r] = v0; bi[r] = lane;
            if (v1 > best[r]) { best[r] = v1; bi[r] = lane + 32; }
            if (lane < 2) {
                float v2 = __ldg(p + 64);
                if (v2 > best[r]) { best[r] = v2; bi[r] = lane + 64; }
            }
        }
#pragma unroll
        for (int r = 0; r < 4; ++r) {
            unsigned kb = __float_as_uint(best[r]);
            kb = (kb & 0x80000000u) ? ~kb : (kb | 0x80000000u);
            unsigned kmax = __reduce_max_sync(0xffffffffu, kb);
            unsigned cand = (kb == kmax) ? (unsigned)bi[r] : 0xffffffffu;
            unsigned imin = __reduce_min_sync(0xffffffffu, cand);
            if (lane == 0) out[base + r] = (float)imin;
        }
    }
}

// ---------------- CRF kernel: 2 sequences per block ----------------
// Block k handles n0=2k, n1=2k+1 (same b -> same L, shared trans/T2).
// Per step: two independent batched-LDS + FFMA2 chains (ILP-2), one barrier.
// Renorm every 4 steps by warp 3 (concurrent, stale-by-2, exact algebra).
__global__ void __launch_bounds__(128, 1) crf_kernel(
    const float* __restrict__ score,       // (B,S,S,K)
    const int*   __restrict__ v_label,     // (B,V)
    const int*   __restrict__ orig_l,      // (B,)
    const int*   __restrict__ role_label,  // (B,V,S)
    const float* __restrict__ start_t,     // (K,)
    const float* __restrict__ trans,       // (K,K)
    const float* __restrict__ end_t,       // (K,)
    float* __restrict__ loss_out)          // scalar
{
    extern __shared__ float sE[];          // [2][TILE] exp(a_score) per seq
    __shared__ __align__(16) float sAa[2][72];
    __shared__ __align__(16) float sAb[2][72];
    __shared__ int   sTagA[SS], sTagB[SS];
    __shared__ float sRed[128];
    __shared__ float sScale[2][2];         // [seq][0]=1/m, [1]=log(m)
    __shared__ int   sLast;

    const int tid = threadIdx.x;
    const int n0 = 2 * blockIdx.x;
    const int n1 = n0 + 1;
    const int b = n0 >> 3;                  // same for n1 (consecutive v)
    const int L = orig_l[b];                // in [S/2, S]
    const float* ascA = score + ((size_t)b * SS + v_label[n0]) * SS * KK;
    const float* ascB = score + ((size_t)b * SS + v_label[n1]) * SS * KK;
    float* sE0 = sE;
    float* sE1 = sE + TILE;

    // tags + alpha pad init
    for (int t = tid; t < SS; t += 128) {
        sTagA[t] = role_label[(size_t)n0 * SS + t];
        sTagB[t] = role_label[(size_t)n1 * SS + t];
    }
    if (tid < 6) {
        sAa[0][66 + tid] = 0.f; sAa[1][66 + tid] = 0.f;
        sAb[0][66 + tid] = 0.f; sAb[1][66 + tid] = 0.f;
    }
    __syncthreads();

    // stage E = exp(a_score) for both sequences (float4 flat copy)
    {
        const float4* sa4 = (const float4*)ascA;
        const float4* sb4 = (const float4*)ascB;
        float4* d0 = (float4*)sE0;
        float4* d1 = (float4*)sE1;
        for (int i4 = tid; i4 < TILE / 4; i4 += 128) {
            float4 v = __ldg(sa4 + i4);
            v.x = __expf(v.x); v.y = __expf(v.y);
            v.z = __expf(v.z); v.w = __expf(v.w);
            d0[i4] = v;
            float4 w = __ldg(sb4 + i4);
            w.x = __expf(w.x); w.y = __expf(w.y);
            w.z = __expf(w.z); w.w = __expf(w.w);
            d1[i4] = w;
        }
    }

    // numerators (emission + gold transitions) for both sequences
    float accA = 0.f, accB = 0.f;
    for (int t = tid; t < L; t += 128) {
        accA += __ldg(ascA + t * KK + sTagA[t]);
        accB += __ldg(ascB + t * KK + sTagB[t]);
    }
    for (int t = tid + 1; t < L; t += 128) {
        accA += __ldg(trans + sTagA[t - 1] * KK + sTagA[t]);
        accB += __ldg(trans + sTagB[t - 1] * KK + sTagB[t]);
    }

    // packed exp(trans) column (shared by both sequences)
    unsigned long long T2[34];
    if (tid < 66) {
#pragma unroll
        for (int p = 0; p < 33; ++p) {
            float lo = __expf(__ldg(trans + (2 * p)     * KK + tid));
            float hi = __expf(__ldg(trans + (2 * p + 1) * KK + tid));
            asm("mov.b64 %0, {%1, %2};" : "=l"(T2[p]) : "f"(lo), "f"(hi));
        }
        T2[33] = 0ull;                      // rows 66,67 are padding
    } else {
#pragma unroll
        for (int p = 0; p < 34; ++p) T2[p] = 0ull;
    }

    // reduce numerator A
    sRed[tid] = accA;
    __syncthreads();
    for (int s = 64; s > 0; s >>= 1) {
        if (tid < s) sRed[tid] += sRed[tid + s];
        __syncthreads();
    }
    float numerA = 0.f;
    if (tid == 0)
        numerA = sRed[0] + __ldg(start_t + sTagA[0]) + __ldg(end_t + sTagA[L - 1]);
    __syncthreads();
    // reduce numerator B
    sRed[tid] = accB;
    __syncthreads();
    for (int s = 64; s > 0; s >>= 1) {
        if (tid < s) sRed[tid] += sRed[tid + s];
        __syncthreads();
    }
    float numerB = 0.f;
    if (tid == 0)
        numerB = sRed[0] + __ldg(start_t + sTagB[0]) + __ldg(end_t + sTagB[L - 1]);

    // alpha0 for both
    if (tid < 66) {
        float st = __expf(start_t[tid]);
        sAa[0][tid] = st * sE0[tid];
        sAb[0][tid] = st * sE1[tid];
    }
    __syncthreads();

    float* AcA = sAa[0]; float* AnA = sAa[1];
    float* AcB = sAb[0]; float* AnB = sAb[1];
    float ClA = 0.f, ClB = 0.f;             // only tid 0's values used
    for (int t = 1; t < L; ++t) {
        const int phase = t & 3;
        if (tid < 66) {
            float invA = 1.f, invB = 1.f;
            if (phase == 0) {               // scales published at t-2
                invA = sScale[0][0]; invB = sScale[1][0];
                if (tid == 0) { ClA += sScale[0][1]; ClB += sScale[1][1]; }
            }
            // batch alpha loads for BOTH sequences, then two FFMA2 chains
            const ulonglong2* A2a = (const ulonglong2*)AcA;
            const ulonglong2* A2b = (const ulonglong2*)AcB;
            unsigned long long qa0[17], qa1[17], qb0[17], qb1[17];
#pragma unroll
            for (int ii = 0; ii < 17; ++ii) {
                ulonglong2 va = A2a[ii]; qa0[ii] = va.x; qa1[ii] = va.y;
                ulonglong2 vb = A2b[ii]; qb0[ii] = vb.x; qb1[ii] = vb.y;
            }
            unsigned long long aA0 = 0ull, aA1 = 0ull, aB0 = 0ull, aB1 = 0ull;
#pragma unroll
            for (int ii = 0; ii < 17; ++ii) {
                ffma2(aA0, qa0[ii], T2[2 * ii]);
                ffma2(aA1, qa1[ii], T2[2 * ii + 1]);
                ffma2(aB0, qb0[ii], T2[2 * ii]);
                ffma2(aB1, qb1[ii], T2[2 * ii + 1]);
            }
            float f0, f1, f2, f3, g0, g1, g2, g3;
            asm("mov.b64 {%0, %1}, %2;" : "=f"(f0), "=f"(f1) : "l"(aA0));
            asm("mov.b64 {%0, %1}, %2;" : "=f"(f2), "=f"(f3) : "l"(aA1));
            asm("mov.b64 {%0, %1}, %2;" : "=f"(g0), "=f"(g1) : "l"(aB0));
            asm("mov.b64 {%0, %1}, %2;" : "=f"(g2), "=f"(g3) : "l"(aB1));
            float sA = (f0 + f2) + (f1 + f3);
            float sB = (g0 + g2) + (g1 + g3);
            AnA[tid] = sA * invA * sE0[t * KK + tid];
            AnB[tid] = sB * invB * sE1[t * KK + tid];
        } else if (tid >= 96 && phase == 2) {
            // warp 3 (concurrent, 1/4 freq): maxes of both alphas, published
            // for application at step t+2.
            const int l = tid - 96;
            float mA = fmaxf(AcA[l], AcA[l + 32]);
            float mB = fmaxf(AcB[l], AcB[l + 32]);
            if (l < 2) { mA = fmaxf(mA, AcA[l + 64]); mB = fmaxf(mB, AcB[l + 64]); }
#pragma unroll
            for (int off = 16; off > 0; off >>= 1) {
                mA = fmaxf(mA, __shfl_xor_sync(0xffffffffu, mA, off));
                mB = fmaxf(mB, __shfl_xor_sync(0xffffffffu, mB, off));
            }
            if (l == 0) {
                sScale[0][0] = 1.f / mA; sScale[0][1] = __logf(mA);
                sScale[1][0] = 1.f / mB; sScale[1][1] = __logf(mB);
            }
        }
        __syncthreads();
        float* tmp;
        tmp = AcA; AcA = AnA; AnA = tmp;
        tmp = AcB; AcB = AnB; AnB = tmp;
    }

    // log_z for both sequences
    float valA = 0.f, valB = 0.f;
    if (tid < 66) {
        float et = __expf(end_t[tid]);
        valA = AcA[tid] * et;
        valB = AcB[tid] * et;
    }
    sRed[tid] = valA;
    __syncthreads();
    for (int s = 64; s > 0; s >>= 1) {
        if (tid < s) sRed[tid] += sRed[tid + s];
        __syncthreads();
    }
    if (tid == 0) g_part[n0] = numerA - (ClA + __logf(sRed[0]));
    __syncthreads();
    sRed[tid] = valB;
    __syncthreads();
    for (int s = 64; s > 0; s >>= 1) {
        if (tid < s) sRed[tid] += sRed[tid + s];
        __syncthreads();
    }
    if (tid == 0) g_part[n1] = numerB - (ClB + __logf(sRed[0]));

    // last block finalizes the loss (and self-resets the counter)
    __threadfence();
    if (tid == 0) {
        unsigned done = atomicAdd(&g_cnt, 1u);
        sLast = (done == NBLK - 1);
    }
    __syncthreads();
    if (sLast) {
        __threadfence();
        sRed[tid] = g_part[tid];
        __syncthreads();
        for (int s = 64; s > 0; s >>= 1) {
            if (tid < s) sRed[tid] += sRed[tid + s];
            __syncthreads();
        }
        if (tid == 0) {
            loss_out[0] = sRed[0] / (float)NSEQ;
            g_cnt = 0u;                      // all NBLK increments already landed
            __threadfence();
        }
    }
}

extern "C" void kernel_launch(void* const* d_in, const int* in_sizes, int n_in,
                              void* d_out, int out_size)
{
    (void)in_sizes; (void)n_in; (void)out_size;
    const float* log_pa     = (const float*)d_in[0];
    const float* score      = (const float*)d_in[1];
    const int*   v_label    = (const int*)d_in[2];
    // d_in[3] = v_l (unused by reference)
    const int*   orig_l     = (const int*)d_in[4];
    const int*   role_label = (const int*)d_in[5];
    const float* start_t    = (const float*)d_in[6];
    const float* trans      = (const float*)d_in[7];
    const float* end_t      = (const float*)d_in[8];
    float* out = (float*)d_out;

    const int smem = 2 * TILE * (int)sizeof(float);  // 135168 B
    cudaFuncSetAttribute((const void*)crf_kernel,
                         cudaFuncAttributeMaxDynamicSharedMemorySize, smem);

    crf_kernel<<<NBLK, 128, smem>>>(
        score, v_label, orig_l, role_label, start_t, trans, end_t, out);
    argmax_kernel<<<2048, 256>>>(log_pa, out + 1);
}